// round 9
// baseline (speedup 1.0000x reference)
#include <cuda_runtime.h>

#define NT   256          // threads per CTA
#define VPT  8            // float4 vectors per thread (8*4*256 = 8192)
#define COLS 8192         // row length
#define CAP  1536         // SMEM candidate buffer capacity
#define GCAP 128          // gather capacity for the hit bin
#define MAXCTA 608        // 152 SMs * 4 CTAs

// Monotone mapping: float -> uint32 such that float order == unsigned order.
__device__ __forceinline__ unsigned mono(float f) {
    unsigned u = __float_as_uint(f);
    return (u & 0x80000000u) ? ~u : (u | 0x80000000u);
}

// Inverse of mono(). Clamps NaN bit patterns (from synthetic bin edges) to +-inf.
__device__ __forceinline__ float inv_mono(unsigned k) {
    unsigned u = (k & 0x80000000u) ? (k & 0x7FFFFFFFu) : ~k;
    if ((u & 0x7F800000u) == 0x7F800000u && (u & 0x007FFFFFu))
        u = (u & 0x80000000u) | 0x7F800000u;
    return __uint_as_float(u);
}

// Single-warp collective: walk a 1024-bin histogram from the TOP bin down, find
// the bin where the cumulative count first reaches rr. All 32 lanes must call.
__device__ __forceinline__ void rank_walk(const unsigned* hist, unsigned rr, int lane,
                                          unsigned& bin_out, unsigned& nr_out) {
    const int base = 1024 - 32 * (lane + 1);   // lane 0 owns the TOP 32 bins
    unsigned s = 0;
#pragma unroll
    for (int i = 0; i < 32; i++) s += hist[base + i];
    unsigned p = s, t;
    t = __shfl_up_sync(0xFFFFFFFFu, p, 1);  if (lane >= 1)  p += t;
    t = __shfl_up_sync(0xFFFFFFFFu, p, 2);  if (lane >= 2)  p += t;
    t = __shfl_up_sync(0xFFFFFFFFu, p, 4);  if (lane >= 4)  p += t;
    t = __shfl_up_sync(0xFFFFFFFFu, p, 8);  if (lane >= 8)  p += t;
    t = __shfl_up_sync(0xFFFFFFFFu, p, 16); if (lane >= 16) p += t;
    const unsigned excl = p - s;
    const bool hit = (excl < rr) && (rr <= p);
    const unsigned m = __ballot_sync(0xFFFFFFFFu, hit);
    unsigned bin = 0, nr = rr;
    if (m) {
        const int hl = __ffs(m) - 1;
        if (lane == hl) {
            unsigned cum = excl;
            for (int b = base + 31; b >= base; b--) {
                cum += hist[b];
                if (cum >= rr) { bin = (unsigned)b; nr = rr - (cum - hist[b]); break; }
            }
        }
        bin = __shfl_sync(0xFFFFFFFFu, bin, hl);
        nr  = __shfl_sync(0xFFFFFFFFu, nr, hl);
    }
    bin_out = bin; nr_out = nr;
}

// Issue async copy of one row (32 KB) into the SMEM buffer and commit the group.
__device__ __forceinline__ void prefetch_row(const float4* __restrict__ rp,
                                             unsigned srow_addr, int tid) {
#pragma unroll
    for (int i = 0; i < VPT; i++) {
        const unsigned dst = srow_addr + (unsigned)(tid + i * NT) * 16u;
        asm volatile("cp.async.cg.shared.global [%0], [%1], 16;\n"
                     :: "r"(dst), "l"(rp + tid + i * NT) : "memory");
    }
    asm volatile("cp.async.commit_group;\n" ::: "memory");
}

__global__ void __launch_bounds__(NT, 4) ksparse_kernel(const float* __restrict__ in,
                                                        const int* __restrict__ kp,
                                                        float* __restrict__ out,
                                                        int rows) {
    __shared__ float4   srow[COLS / 4];  // 32 KB: async-prefetched row
    __shared__ unsigned buf[CAP];        // 6 KB: bracket-relative candidate keys
    __shared__ unsigned hist[1024];      // 4 KB
    __shared__ unsigned g[GCAP];         // hit-bin gather
    __shared__ unsigned warpsum[8];
    __shared__ int s_cnt, s_gn;
    __shared__ unsigned s_hibin, s_lobin, s_bin, s_rank;
    __shared__ float s_T;

    const int tid  = threadIdx.x;
    const int lane = tid & 31;
    const int wid  = tid >> 5;
    const int stride = gridDim.x;

    const unsigned srow_addr = (unsigned)__cvta_generic_to_shared(srow);
    const int K = kp ? __ldg(kp) : 512;
    const unsigned r = (unsigned)(K + 1);   // rank of threshold (descending, 1-indexed)

    int row = blockIdx.x;
    if (row < rows)
        prefetch_row((const float4*)(in + (size_t)row * COLS), srow_addr, tid);

    for (; row < rows; row += stride) {
        float4* op = (float4*)(out + (size_t)row * COLS);

        // Zero per-row state while the prefetch is still in flight.
        hist[tid] = 0; hist[tid + NT] = 0; hist[tid + 2 * NT] = 0; hist[tid + 3 * NT] = 0;
        if (tid == 0) s_gn = 0;
        asm volatile("cp.async.wait_group 0;\n" ::: "memory");
        __syncthreads();

        // Row SMEM -> registers.
        float4 v[VPT];
#pragma unroll
        for (int i = 0; i < VPT; i++) v[i] = srow[tid + i * NT];
        __syncthreads();   // everyone done reading srow before it is overwritten

        // Kick off next row's prefetch; it overlaps the whole selection below.
        {
            const int nrow = row + stride;
            if (nrow < rows)
                prefetch_row((const float4*)(in + (size_t)nrow * COLS), srow_addr, tid);
        }

        // ---- Phase 1: sample histogram (2 samples/thread = 512) ----
        atomicAdd(&hist[mono(v[0].x) >> 22], 1u);
        atomicAdd(&hist[mono(v[4].x) >> 22], 1u);
        __syncthreads();

        // ---- Phase 2: bracket pivots — hi walk (warp 0) and lo walk (warp 1) parallel ----
        {
            const float ex = (float)r * (512.0f / (float)COLS);   // expected sample rank
            const float sd = sqrtf(ex + 4.0f);
            if (wid == 0) {
                int hi_cut = (int)(ex - 5.0f * sd - 2.0f); if (hi_cut < 0) hi_cut = 0;
                unsigned b, nr;
                rank_walk(hist, (unsigned)hi_cut + 1u, lane, b, nr);
                if (lane == 0) s_hibin = b;
            } else if (wid == 1) {
                int lo_cut = (int)(ex + 5.0f * sd + 8.0f); if (lo_cut > 512) lo_cut = 512;
                unsigned b, nr;
                rank_walk(hist, (unsigned)lo_cut, lane, b, nr);
                if (lane == 0) s_lobin = b;
            }
        }
        __syncthreads();
        const unsigned HI_bin = s_hibin, LO_bin = s_lobin;
        const unsigned khi = ((HI_bin + 1u) << 22) - 1u;          // key of U_hi
        const unsigned klo = (LO_bin << 22) - 1u;                 // key of U_lo (LO_bin>0)
        const float U_hi = inv_mono(khi);
        const float U_lo = (LO_bin == 0u) ? __int_as_float(0xFF800000) : inv_mono(klo);

        // ---- Phase 3a: predicate masks over registers (no atomics, no branches) ----
        unsigned mhi = 0, mbr = 0;
#pragma unroll
        for (int i = 0; i < VPT; i++) {
#pragma unroll
            for (int j = 0; j < 4; j++) {
                const float x = (&v[i].x)[j];
                const bool a = x > U_hi;
                const bool b = (x > U_lo) && !a;
                mhi |= ((unsigned)a) << (i * 4 + j);
                mbr |= ((unsigned)b) << (i * 4 + j);
            }
        }
        // Packed block scan: high 16 bits = count(>U_hi), low 16 = bracket count.
        const unsigned packed = ((unsigned)__popc(mhi) << 16) | (unsigned)__popc(mbr);
        unsigned inc = packed, t;
        t = __shfl_up_sync(0xFFFFFFFFu, inc, 1);  if (lane >= 1)  inc += t;
        t = __shfl_up_sync(0xFFFFFFFFu, inc, 2);  if (lane >= 2)  inc += t;
        t = __shfl_up_sync(0xFFFFFFFFu, inc, 4);  if (lane >= 4)  inc += t;
        t = __shfl_up_sync(0xFFFFFFFFu, inc, 8);  if (lane >= 8)  inc += t;
        t = __shfl_up_sync(0xFFFFFFFFu, inc, 16); if (lane >= 16) inc += t;
        if (lane == 31) warpsum[wid] = inc;
        __syncthreads();
        if (wid == 0) {
            unsigned w = (lane < 8) ? warpsum[lane] : 0;
            t = __shfl_up_sync(0xFFFFFFFFu, w, 1); if (lane >= 1) w += t;
            t = __shfl_up_sync(0xFFFFFFFFu, w, 2); if (lane >= 2) w += t;
            t = __shfl_up_sync(0xFFFFFFFFu, w, 4); if (lane >= 4) w += t;
            if (lane < 8) warpsum[lane] = w;
        }
        __syncthreads();
        const unsigned tot  = warpsum[7];
        const unsigned excl = (wid ? warpsum[wid - 1] : 0u) + inc - packed;
        const int CHI  = (int)(tot >> 16);
        const int nbuf = (int)(tot & 0xFFFFu);
        int pos = (int)(excl & 0xFFFFu);

        // ---- Phase 3b: push bracket-relative keys to owned slots ----
#pragma unroll
        for (int i = 0; i < VPT; i++) {
#pragma unroll
            for (int j = 0; j < 4; j++) {
                if ((mbr >> (i * 4 + j)) & 1u) {
                    if (pos < CAP) buf[pos] = mono((&v[i].x)[j]) - klo - 1u;
                    pos++;
                }
            }
        }
        __syncthreads();

        const int rr0 = (int)r - CHI;
        const unsigned span = khi - klo;               // bracket width in key units
        const bool ok = (LO_bin > 0u) && (span <= (1u << 24)) &&
                        (nbuf <= CAP) && (rr0 >= 1) && (rr0 <= nbuf);
        bool need_fb = !ok;                            // block-uniform

        if (ok) {
            // ---- Phase 4a: one 10-bit level over bracket-relative keys ----
            hist[tid] = 0; hist[tid + NT] = 0; hist[tid + 2 * NT] = 0; hist[tid + 3 * NT] = 0;
            __syncthreads();
            for (int i = tid; i < nbuf; i += NT)
                atomicAdd(&hist[buf[i] >> 14], 1u);
            __syncthreads();
            if (wid == 0) {
                unsigned b, nr;
                rank_walk(hist, (unsigned)rr0, lane, b, nr);
                if (lane == 0) { s_bin = b; s_rank = nr; }
            }
            __syncthreads();
            const unsigned bin = s_bin;
            const unsigned nr  = s_rank;
            const int m = (int)hist[bin];
            if (m <= GCAP) {
                // ---- Phase 4b: gather hit-bin keys ----
                for (int i = tid; i < nbuf; i += NT) {
                    const unsigned d = buf[i];
                    if ((d >> 14) == bin) {
                        const int p = atomicAdd(&s_gn, 1);
                        if (p < GCAP) g[p] = d;
                    }
                }
                __syncthreads();
                // ---- Phase 4c: warp 0 selects the nr-th largest among m keys ----
                if (wid == 0) {
                    unsigned my[4]; int gt[4] = {0,0,0,0}, ge[4] = {0,0,0,0};
#pragma unroll
                    for (int q = 0; q < 4; q++)
                        my[q] = (lane + 32 * q < m) ? g[lane + 32 * q] : 0u;
                    for (int i = 0; i < m; i++) {
                        const unsigned ki = g[i];
#pragma unroll
                        for (int q = 0; q < 4; q++) {
                            gt[q] += (ki > my[q]);
                            ge[q] += (ki >= my[q]);
                        }
                    }
                    bool found = false; unsigned sel = 0;
#pragma unroll
                    for (int q = 0; q < 4; q++) {
                        const bool hit = (lane + 32 * q < m) &&
                                         ((unsigned)gt[q] < nr) && (nr <= (unsigned)ge[q]);
                        if (hit && !found) { sel = my[q]; found = true; }
                    }
                    const unsigned bm = __ballot_sync(0xFFFFFFFFu, found);
                    if (bm && lane == __ffs(bm) - 1) s_T = inv_mono(klo + 1u + sel);
                }
            } else {
                need_fb = true;                        // block-uniform (m from SMEM)
            }
        }
        __syncthreads();

        if (need_fb) {
            // ---- Fallback: exact 32-bit bisection over register data (rare) ----
            unsigned pfx = 0;
            for (int bit = 31; bit >= 0; bit--) {
                const unsigned cand = pfx | (1u << bit);
                int c = 0;
#pragma unroll
                for (int i = 0; i < VPT; i++) {
                    c += (mono(v[i].x) >= cand) + (mono(v[i].y) >= cand)
                       + (mono(v[i].z) >= cand) + (mono(v[i].w) >= cand);
                }
#pragma unroll
                for (int off = 16; off; off >>= 1) c += __shfl_down_sync(0xFFFFFFFFu, c, off);
                __syncthreads();
                if (tid == 0) s_cnt = 0;
                __syncthreads();
                if (lane == 0) atomicAdd(&s_cnt, c);
                __syncthreads();
                if ((unsigned)s_cnt >= r) pfx = cand;
            }
            if (tid == 0) s_T = inv_mono(pfx);
            __syncthreads();
        }
        const float T = s_T;

        // ---- Phase 5: mask from registers, single global write ----
#pragma unroll
        for (int i = 0; i < VPT; i++) {
            float4 o;
            o.x = v[i].x > T ? v[i].x : 0.0f;
            o.y = v[i].y > T ? v[i].y : 0.0f;
            o.z = v[i].z > T ? v[i].z : 0.0f;
            o.w = v[i].w > T ? v[i].w : 0.0f;
            op[tid + i * NT] = o;
        }
        __syncthreads();   // keep s_T stable until all threads consumed it
    }
}

extern "C" void kernel_launch(void* const* d_in, const int* in_sizes, int n_in,
                              void* d_out, int out_size) {
    const float* in = (const float*)d_in[0];
    const int*   kp = (n_in >= 2) ? (const int*)d_in[1] : nullptr;
    float* out = (float*)d_out;
    const int rows = in_sizes[0] / COLS;
    const int grid = rows < MAXCTA ? rows : MAXCTA;
    ksparse_kernel<<<grid, NT>>>(in, kp, out, rows);
}

// round 10
// speedup vs baseline: 2.2648x; 2.2648x over previous
#include <cuda_runtime.h>

#define NT   256          // threads per CTA
#define VPT  8            // float4 vectors per thread (8*4*256 = 8192)
#define COLS 8192         // row length
#define CAP  2048         // SMEM candidate buffer capacity
#define GCAP 128          // gather capacity for the hit bin

// Monotone mapping: float -> uint32 such that float order == unsigned order.
__device__ __forceinline__ unsigned mono(float f) {
    unsigned u = __float_as_uint(f);
    return (u & 0x80000000u) ? ~u : (u | 0x80000000u);
}

// Inverse of mono(). Clamps NaN bit patterns (from synthetic bin edges) to +-inf.
__device__ __forceinline__ float inv_mono(unsigned k) {
    unsigned u = (k & 0x80000000u) ? (k & 0x7FFFFFFFu) : ~k;
    if ((u & 0x7F800000u) == 0x7F800000u && (u & 0x007FFFFFu))
        u = (u & 0x80000000u) | 0x7F800000u;
    return __uint_as_float(u);
}

// Single-warp collective: walk a 1024-bin histogram from the TOP bin down, find
// the bin where the cumulative count first reaches rr. All 32 lanes must call.
__device__ __forceinline__ void rank_walk(const unsigned* hist, unsigned rr, int lane,
                                          unsigned& bin_out, unsigned& nr_out) {
    const int base = 1024 - 32 * (lane + 1);   // lane 0 owns the TOP 32 bins
    unsigned s = 0;
#pragma unroll
    for (int i = 0; i < 32; i++) s += hist[base + i];
    unsigned p = s, t;
    t = __shfl_up_sync(0xFFFFFFFFu, p, 1);  if (lane >= 1)  p += t;
    t = __shfl_up_sync(0xFFFFFFFFu, p, 2);  if (lane >= 2)  p += t;
    t = __shfl_up_sync(0xFFFFFFFFu, p, 4);  if (lane >= 4)  p += t;
    t = __shfl_up_sync(0xFFFFFFFFu, p, 8);  if (lane >= 8)  p += t;
    t = __shfl_up_sync(0xFFFFFFFFu, p, 16); if (lane >= 16) p += t;
    const unsigned excl = p - s;
    const bool hit = (excl < rr) && (rr <= p);
    const unsigned m = __ballot_sync(0xFFFFFFFFu, hit);
    unsigned bin = 0, nr = rr;
    if (m) {
        const int hl = __ffs(m) - 1;
        if (lane == hl) {
            unsigned cum = excl;
            for (int b = base + 31; b >= base; b--) {
                cum += hist[b];
                if (cum >= rr) { bin = (unsigned)b; nr = rr - (cum - hist[b]); break; }
            }
        }
        bin = __shfl_sync(0xFFFFFFFFu, bin, hl);
        nr  = __shfl_sync(0xFFFFFFFFu, nr, hl);
    }
    bin_out = bin; nr_out = nr;
}

__global__ void __launch_bounds__(NT, 4) ksparse_kernel(const float* __restrict__ in,
                                                        const int* __restrict__ kp,
                                                        float* __restrict__ out) {
    __shared__ unsigned buf[CAP];      // 8 KB: klo-relative candidate keys
    __shared__ unsigned hist[1024];    // 4 KB
    __shared__ unsigned g[GCAP];       // hit-bin gather
    __shared__ unsigned warpsum[8];
    __shared__ int s_cnt, s_gn;
    __shared__ unsigned s_lobin, s_bin, s_rank;
    __shared__ float s_T;

    const int tid  = threadIdx.x;
    const int lane = tid & 31;
    const int wid  = tid >> 5;

    const float4* rp = (const float4*)(in  + (size_t)blockIdx.x * COLS);
    float4*       op = (float4*)      (out + (size_t)blockIdx.x * COLS);

    // Entire row resident in registers: one global read.
    float4 v[VPT];
#pragma unroll
    for (int i = 0; i < VPT; i++) v[i] = rp[tid + i * NT];

    const int K = kp ? __ldg(kp) : 512;
    const unsigned r = (unsigned)(K + 1);   // rank of threshold (descending, 1-indexed)

    hist[tid] = 0; hist[tid + NT] = 0; hist[tid + 2 * NT] = 0; hist[tid + 3 * NT] = 0;
    if (tid == 0) s_gn = 0;
    __syncthreads();

    // ---- Phase 1: sample histogram (2 samples/thread = 512) ----
    atomicAdd(&hist[mono(v[0].x) >> 22], 1u);
    atomicAdd(&hist[mono(v[4].x) >> 22], 1u);
    __syncthreads();

    // ---- Phase 2: single lower pivot (warp 0): U_lo below T with 5-sigma margin ----
    if (wid == 0) {
        const float ex = (float)r * (512.0f / (float)COLS);   // expected sample rank
        const float sd = sqrtf(ex + 4.0f);
        int lo_cut = (int)(ex + 5.0f * sd + 8.0f); if (lo_cut > 512) lo_cut = 512;
        unsigned b, nr;
        rank_walk(hist, (unsigned)lo_cut, lane, b, nr);
        if (lane == 0) s_lobin = b;
    }
    __syncthreads();
    const unsigned LO_bin = s_lobin;
    const unsigned klo = (LO_bin << 22) - 1u;                 // key of U_lo (LO_bin>0)
    const float U_lo = (LO_bin == 0u) ? __int_as_float(0xFF800000) : inv_mono(klo);

    // ---- Phase 3a: single-compare mask over registers ----
    unsigned mbr = 0;
#pragma unroll
    for (int i = 0; i < VPT; i++) {
#pragma unroll
        for (int j = 0; j < 4; j++)
            mbr |= ((unsigned)((&v[i].x)[j] > U_lo)) << (i * 4 + j);
    }
    // Block scan of candidate counts -> total nbuf + per-thread offset.
    const unsigned cnt = (unsigned)__popc(mbr);
    unsigned inc = cnt, t;
    t = __shfl_up_sync(0xFFFFFFFFu, inc, 1);  if (lane >= 1)  inc += t;
    t = __shfl_up_sync(0xFFFFFFFFu, inc, 2);  if (lane >= 2)  inc += t;
    t = __shfl_up_sync(0xFFFFFFFFu, inc, 4);  if (lane >= 4)  inc += t;
    t = __shfl_up_sync(0xFFFFFFFFu, inc, 8);  if (lane >= 8)  inc += t;
    t = __shfl_up_sync(0xFFFFFFFFu, inc, 16); if (lane >= 16) inc += t;
    if (lane == 31) warpsum[wid] = inc;
    __syncthreads();
    if (wid == 0) {
        unsigned w = (lane < 8) ? warpsum[lane] : 0;
        t = __shfl_up_sync(0xFFFFFFFFu, w, 1); if (lane >= 1) w += t;
        t = __shfl_up_sync(0xFFFFFFFFu, w, 2); if (lane >= 2) w += t;
        t = __shfl_up_sync(0xFFFFFFFFu, w, 4); if (lane >= 4) w += t;
        if (lane < 8) warpsum[lane] = w;
    }
    __syncthreads();
    const int nbuf = (int)warpsum[7];
    int pos = (int)((wid ? warpsum[wid - 1] : 0u) + inc - cnt);

    // ---- Phase 3b: push klo-relative keys (full precision) to owned slots ----
#pragma unroll
    for (int i = 0; i < VPT; i++) {
#pragma unroll
        for (int j = 0; j < 4; j++) {
            if ((mbr >> (i * 4 + j)) & 1u) {
                if (pos < CAP) buf[pos] = mono((&v[i].x)[j]) - klo;   // >= 1, no wrap
                pos++;
            }
        }
    }
    __syncthreads();

    const bool ok = (LO_bin > 0u) && (nbuf <= CAP) && ((int)r <= nbuf);
    bool need_fb = !ok;                            // block-uniform

    if (ok) {
        // ---- Phase 4a: one clamped 10-bit level; rank r directly ----
        hist[tid] = 0; hist[tid + NT] = 0; hist[tid + 2 * NT] = 0; hist[tid + 3 * NT] = 0;
        __syncthreads();
        for (int i = tid; i < nbuf; i += NT) {
            unsigned dig = buf[i] >> 14;
            dig = dig > 1023u ? 1023u : dig;       // clamp: monotone for huge keys
            atomicAdd(&hist[dig], 1u);
        }
        __syncthreads();
        if (wid == 0) {
            unsigned b, nr;
            rank_walk(hist, r, lane, b, nr);
            if (lane == 0) { s_bin = b; s_rank = nr; }
        }
        __syncthreads();
        const unsigned bin = s_bin;
        const unsigned nr  = s_rank;
        const int m = (int)hist[bin];
        if (m <= GCAP) {
            // ---- Phase 4b: gather hit-bin keys (full values, exact even if clamped) ----
            for (int i = tid; i < nbuf; i += NT) {
                const unsigned d = buf[i];
                unsigned dig = d >> 14;
                dig = dig > 1023u ? 1023u : dig;
                if (dig == bin) {
                    const int p = atomicAdd(&s_gn, 1);
                    if (p < GCAP) g[p] = d;
                }
            }
            __syncthreads();
            // ---- Phase 4c: warp 0 selects the nr-th largest among m keys ----
            if (wid == 0) {
                unsigned my[4]; int gt[4] = {0,0,0,0}, ge[4] = {0,0,0,0};
#pragma unroll
                for (int q = 0; q < 4; q++)
                    my[q] = (lane + 32 * q < m) ? g[lane + 32 * q] : 0u;
                for (int i = 0; i < m; i++) {
                    const unsigned ki = g[i];
#pragma unroll
                    for (int q = 0; q < 4; q++) {
                        gt[q] += (ki > my[q]);
                        ge[q] += (ki >= my[q]);
                    }
                }
                bool found = false; unsigned sel = 0;
#pragma unroll
                for (int q = 0; q < 4; q++) {
                    const bool hit = (lane + 32 * q < m) &&
                                     ((unsigned)gt[q] < nr) && (nr <= (unsigned)ge[q]);
                    if (hit && !found) { sel = my[q]; found = true; }
                }
                const unsigned bm = __ballot_sync(0xFFFFFFFFu, found);
                if (bm && lane == __ffs(bm) - 1) s_T = inv_mono(klo + sel);
            }
        } else {
            need_fb = true;                        // block-uniform (m from SMEM)
        }
    }
    __syncthreads();

    if (need_fb) {
        // ---- Fallback: exact 32-bit bisection over register data (rare) ----
        unsigned pfx = 0;
        for (int bit = 31; bit >= 0; bit--) {
            const unsigned cand = pfx | (1u << bit);
            int c = 0;
#pragma unroll
            for (int i = 0; i < VPT; i++) {
                c += (mono(v[i].x) >= cand) + (mono(v[i].y) >= cand)
                   + (mono(v[i].z) >= cand) + (mono(v[i].w) >= cand);
            }
#pragma unroll
            for (int off = 16; off; off >>= 1) c += __shfl_down_sync(0xFFFFFFFFu, c, off);
            __syncthreads();
            if (tid == 0) s_cnt = 0;
            __syncthreads();
            if (lane == 0) atomicAdd(&s_cnt, c);
            __syncthreads();
            if ((unsigned)s_cnt >= r) pfx = cand;
        }
        if (tid == 0) s_T = inv_mono(pfx);
        __syncthreads();
    }
    const float T = s_T;

    // ---- Phase 5: mask from registers, single global write ----
#pragma unroll
    for (int i = 0; i < VPT; i++) {
        float4 o;
        o.x = v[i].x > T ? v[i].x : 0.0f;
        o.y = v[i].y > T ? v[i].y : 0.0f;
        o.z = v[i].z > T ? v[i].z : 0.0f;
        o.w = v[i].w > T ? v[i].w : 0.0f;
        op[tid + i * NT] = o;
    }
}

extern "C" void kernel_launch(void* const* d_in, const int* in_sizes, int n_in,
                              void* d_out, int out_size) {
    const float* in = (const float*)d_in[0];
    const int*   kp = (n_in >= 2) ? (const int*)d_in[1] : nullptr;
    float* out = (float*)d_out;
    const int rows = in_sizes[0] / COLS;
    ksparse_kernel<<<rows, NT>>>(in, kp, out);
}

// round 11
// speedup vs baseline: 2.8700x; 1.2672x over previous
#include <cuda_runtime.h>

#define NT   256          // threads per CTA
#define VPT  8            // float4 vectors per thread (8*4*256 = 8192)
#define COLS 8192         // row length
#define CAP  2048         // SMEM candidate buffer capacity
#define GCAP 128          // gather capacity for the hit bin

// Monotone mapping: float -> uint32 such that float order == unsigned order.
__device__ __forceinline__ unsigned mono(float f) {
    unsigned u = __float_as_uint(f);
    return (u & 0x80000000u) ? ~u : (u | 0x80000000u);
}

// Inverse of mono(). Clamps NaN bit patterns to +-inf.
__device__ __forceinline__ float inv_mono(unsigned k) {
    unsigned u = (k & 0x80000000u) ? (k & 0x7FFFFFFFu) : ~k;
    if ((u & 0x7F800000u) == 0x7F800000u && (u & 0x007FFFFFu))
        u = (u & 0x80000000u) | 0x7F800000u;
    return __uint_as_float(u);
}

// Single-warp collective: walk a 1024-bin histogram from the TOP bin down, find
// the bin where the cumulative count first reaches rr. All 32 lanes must call.
__device__ __forceinline__ void rank_walk(const unsigned* hist, unsigned rr, int lane,
                                          unsigned& bin_out, unsigned& nr_out) {
    const int base = 1024 - 32 * (lane + 1);   // lane 0 owns the TOP 32 bins
    unsigned s = 0;
#pragma unroll
    for (int i = 0; i < 32; i++) s += hist[base + i];
    unsigned p = s, t;
    t = __shfl_up_sync(0xFFFFFFFFu, p, 1);  if (lane >= 1)  p += t;
    t = __shfl_up_sync(0xFFFFFFFFu, p, 2);  if (lane >= 2)  p += t;
    t = __shfl_up_sync(0xFFFFFFFFu, p, 4);  if (lane >= 4)  p += t;
    t = __shfl_up_sync(0xFFFFFFFFu, p, 8);  if (lane >= 8)  p += t;
    t = __shfl_up_sync(0xFFFFFFFFu, p, 16); if (lane >= 16) p += t;
    const unsigned excl = p - s;
    const bool hit = (excl < rr) && (rr <= p);
    const unsigned m = __ballot_sync(0xFFFFFFFFu, hit);
    unsigned bin = 0, nr = rr;
    if (m) {
        const int hl = __ffs(m) - 1;
        if (lane == hl) {
            unsigned cum = excl;
            for (int b = base + 31; b >= base; b--) {
                cum += hist[b];
                if (cum >= rr) { bin = (unsigned)b; nr = rr - (cum - hist[b]); break; }
            }
        }
        bin = __shfl_sync(0xFFFFFFFFu, bin, hl);
        nr  = __shfl_sync(0xFFFFFFFFu, nr, hl);
    }
    bin_out = bin; nr_out = nr;
}

__global__ void __launch_bounds__(NT, 4) ksparse_kernel(const float* __restrict__ in,
                                                        const int* __restrict__ kp,
                                                        float* __restrict__ out) {
    __shared__ unsigned buf[CAP];      // 8 KB: klo-relative candidate keys
    __shared__ unsigned hist[1024];    // 4 KB
    __shared__ unsigned g[GCAP];       // hit-bin gather
    __shared__ unsigned warpsum[8];
    __shared__ int s_cnt, s_gn;
    __shared__ unsigned s_bin, s_rank;
    __shared__ float s_T;

    const int tid  = threadIdx.x;
    const int lane = tid & 31;
    const int wid  = tid >> 5;

    const float4* rp = (const float4*)(in  + (size_t)blockIdx.x * COLS);
    float4*       op = (float4*)      (out + (size_t)blockIdx.x * COLS);

    // Entire row resident in registers: one global read.
    float4 v[VPT];
#pragma unroll
    for (int i = 0; i < VPT; i++) v[i] = rp[tid + i * NT];

    const int K = kp ? __ldg(kp) : 512;
    const unsigned r = (unsigned)(K + 1);   // rank of threshold (descending, 1-indexed)

    // ---- Analytic pivot: U_lo below T with large margin (no samples, no SMEM).
    // Distribution assumption affects ONLY performance; the guards below route
    // any mismatch to the exact fallback.
    float p = (2.5f * (float)r + 160.0f) / (float)COLS;
    p = fminf(0.499f, fmaxf(p, 0.015625f));
    const float U_lo = normcdfinvf(1.0f - p);
    const unsigned klo = mono(U_lo);

    // ---- Phase 3a: single-compare mask over registers ----
    unsigned mbr = 0;
#pragma unroll
    for (int i = 0; i < VPT; i++) {
#pragma unroll
        for (int j = 0; j < 4; j++)
            mbr |= ((unsigned)((&v[i].x)[j] > U_lo)) << (i * 4 + j);
    }

    // Zero per-row state; ordered before use by the scan's barriers.
    hist[tid] = 0; hist[tid + NT] = 0; hist[tid + 2 * NT] = 0; hist[tid + 3 * NT] = 0;
    if (tid == 0) s_gn = 0;

    // Block scan of candidate counts -> total nbuf + per-thread offset.
    const unsigned cnt = (unsigned)__popc(mbr);
    unsigned inc = cnt, t;
    t = __shfl_up_sync(0xFFFFFFFFu, inc, 1);  if (lane >= 1)  inc += t;
    t = __shfl_up_sync(0xFFFFFFFFu, inc, 2);  if (lane >= 2)  inc += t;
    t = __shfl_up_sync(0xFFFFFFFFu, inc, 4);  if (lane >= 4)  inc += t;
    t = __shfl_up_sync(0xFFFFFFFFu, inc, 8);  if (lane >= 8)  inc += t;
    t = __shfl_up_sync(0xFFFFFFFFu, inc, 16); if (lane >= 16) inc += t;
    if (lane == 31) warpsum[wid] = inc;
    __syncthreads();
    if (wid == 0) {
        unsigned w = (lane < 8) ? warpsum[lane] : 0;
        t = __shfl_up_sync(0xFFFFFFFFu, w, 1); if (lane >= 1) w += t;
        t = __shfl_up_sync(0xFFFFFFFFu, w, 2); if (lane >= 2) w += t;
        t = __shfl_up_sync(0xFFFFFFFFu, w, 4); if (lane >= 4) w += t;
        if (lane < 8) warpsum[lane] = w;
    }
    __syncthreads();
    const int nbuf = (int)warpsum[7];
    int pos = (int)((wid ? warpsum[wid - 1] : 0u) + inc - cnt);

    // ---- Phase 3b: push klo-relative keys (full precision) to owned slots ----
#pragma unroll
    for (int i = 0; i < VPT; i++) {
#pragma unroll
        for (int j = 0; j < 4; j++) {
            if ((mbr >> (i * 4 + j)) & 1u) {
                if (pos < CAP) buf[pos] = mono((&v[i].x)[j]) - klo;   // >= 1, no wrap
                pos++;
            }
        }
    }
    __syncthreads();

    const bool ok = (nbuf <= CAP) && ((int)r <= nbuf);
    bool need_fb = !ok;                            // block-uniform

    if (ok) {
        // ---- Phase 4a: one clamped 10-bit level; rank r directly ----
        for (int i = tid; i < nbuf; i += NT) {
            unsigned dig = buf[i] >> 14;
            dig = dig > 1023u ? 1023u : dig;       // clamp: monotone for huge keys
            atomicAdd(&hist[dig], 1u);
        }
        __syncthreads();
        if (wid == 0) {
            unsigned b, nr;
            rank_walk(hist, r, lane, b, nr);
            if (lane == 0) { s_bin = b; s_rank = nr; }
        }
        __syncthreads();
        const unsigned bin = s_bin;
        const unsigned nr  = s_rank;
        const int m = (int)hist[bin];
        if (m <= GCAP) {
            // ---- Phase 4b: gather hit-bin keys (full values, exact even if clamped) ----
            for (int i = tid; i < nbuf; i += NT) {
                const unsigned d = buf[i];
                unsigned dig = d >> 14;
                dig = dig > 1023u ? 1023u : dig;
                if (dig == bin) {
                    const int pg = atomicAdd(&s_gn, 1);
                    if (pg < GCAP) g[pg] = d;
                }
            }
            __syncthreads();
            // ---- Phase 4c: warp 0 selects the nr-th largest among m keys ----
            if (wid == 0) {
                unsigned my[4]; int gt[4] = {0,0,0,0}, ge[4] = {0,0,0,0};
#pragma unroll
                for (int q = 0; q < 4; q++)
                    my[q] = (lane + 32 * q < m) ? g[lane + 32 * q] : 0u;
                for (int i = 0; i < m; i++) {
                    const unsigned ki = g[i];
#pragma unroll
                    for (int q = 0; q < 4; q++) {
                        gt[q] += (ki > my[q]);
                        ge[q] += (ki >= my[q]);
                    }
                }
                bool found = false; unsigned sel = 0;
#pragma unroll
                for (int q = 0; q < 4; q++) {
                    const bool hit = (lane + 32 * q < m) &&
                                     ((unsigned)gt[q] < nr) && (nr <= (unsigned)ge[q]);
                    if (hit && !found) { sel = my[q]; found = true; }
                }
                const unsigned bm = __ballot_sync(0xFFFFFFFFu, found);
                if (bm && lane == __ffs(bm) - 1) s_T = inv_mono(klo + sel);
            }
        } else {
            need_fb = true;                        // block-uniform (m from SMEM)
        }
    }
    __syncthreads();

    if (need_fb) {
        // ---- Fallback: exact 32-bit bisection over register data (rare) ----
        unsigned pfx = 0;
        for (int bit = 31; bit >= 0; bit--) {
            const unsigned cand = pfx | (1u << bit);
            int c = 0;
#pragma unroll
            for (int i = 0; i < VPT; i++) {
                c += (mono(v[i].x) >= cand) + (mono(v[i].y) >= cand)
                   + (mono(v[i].z) >= cand) + (mono(v[i].w) >= cand);
            }
#pragma unroll
            for (int off = 16; off; off >>= 1) c += __shfl_down_sync(0xFFFFFFFFu, c, off);
            __syncthreads();
            if (tid == 0) s_cnt = 0;
            __syncthreads();
            if (lane == 0) atomicAdd(&s_cnt, c);
            __syncthreads();
            if ((unsigned)s_cnt >= r) pfx = cand;
        }
        if (tid == 0) s_T = inv_mono(pfx);
        __syncthreads();
    }
    const float T = s_T;

    // ---- Phase 5: mask from registers, single global write ----
#pragma unroll
    for (int i = 0; i < VPT; i++) {
        float4 o;
        o.x = v[i].x > T ? v[i].x : 0.0f;
        o.y = v[i].y > T ? v[i].y : 0.0f;
        o.z = v[i].z > T ? v[i].z : 0.0f;
        o.w = v[i].w > T ? v[i].w : 0.0f;
        op[tid + i * NT] = o;
    }
}

extern "C" void kernel_launch(void* const* d_in, const int* in_sizes, int n_in,
                              void* d_out, int out_size) {
    const float* in = (const float*)d_in[0];
    const int*   kp = (n_in >= 2) ? (const int*)d_in[1] : nullptr;
    float* out = (float*)d_out;
    const int rows = in_sizes[0] / COLS;
    ksparse_kernel<<<rows, NT>>>(in, kp, out);
}